// round 1
// baseline (speedup 1.0000x reference)
#include <cuda_runtime.h>

// ---------------------------------------------------------------------------
// Fused FourierLayer MoE kernel for fixed shapes:
//   B=2, T=32, C=1, H=16, W=16, D=128, E=9, TOP_K=2  ->  N = B*H*W = 512 tokens
// One block per token. Everything (fuse GEMM, rFFT gating, top-2 expert GEMMs,
// log-sum-exp combine) happens in shared memory; no global scratch needed.
// ---------------------------------------------------------------------------

#define FFMA2(d, a, b, c) \
    asm("fma.rn.f32x2 %0, %1, %2, %3;" : "=l"(d) : "l"(a), "l"(b), "l"(c))

__device__ __forceinline__ unsigned long long dup_f32(float v) {
    unsigned int u = __float_as_uint(v);
    unsigned long long r;
    asm("mov.b64 %0, {%1, %1};" : "=l"(r) : "r"(u));
    return r;
}

__device__ __forceinline__ void unpack_f32x2(unsigned long long p, float &lo, float &hi) {
    unsigned int a, b;
    asm("mov.b64 {%0, %1}, %2;" : "=r"(a), "=r"(b) : "l"(p));
    lo = __uint_as_float(a);
    hi = __uint_as_float(b);
}

// e^x for x <= 0, FMA-pipe only (no MUFU). 2^f poly (Taylor, f in [-0.5, 0.5]),
// |rel err| < ~2e-7. Safe down to underflow (clamped at 2^-126 scale).
__device__ __forceinline__ float exp_neg_fast(float x) {
    float z = x * 1.4426950408889634f;   // x * log2(e)
    z = fmaxf(z, -126.0f);
    float fn = rintf(z);
    float f  = z - fn;                   // f in [-0.5, 0.5]
    float p  = 1.5403506e-4f;
    p = fmaf(p, f, 1.3333558e-3f);
    p = fmaf(p, f, 9.6181291e-3f);
    p = fmaf(p, f, 5.5504109e-2f);
    p = fmaf(p, f, 2.4022651e-1f);
    p = fmaf(p, f, 6.9314718e-1f);
    p = fmaf(p, f, 1.0f);
    int ifn = (int)fn;
    float scale = __int_as_float((ifn + 127) << 23);   // 2^ifn
    return p * scale;
}

// cos(2*pi*k/32), k = 0..31.  sin(2*pi*k/32) = table[(k+24) & 31].
__device__ const float g_cos32[32] = {
     1.0f,           0.98078528040f,  0.92387953251f,  0.83146961230f,
     0.70710678119f, 0.55557023302f,  0.38268343237f,  0.19509032202f,
     0.0f,          -0.19509032202f, -0.38268343237f, -0.55557023302f,
    -0.70710678119f,-0.83146961230f, -0.92387953251f, -0.98078528040f,
    -1.0f,          -0.98078528040f, -0.92387953251f, -0.83146961230f,
    -0.70710678119f,-0.55557023302f, -0.38268343237f, -0.19509032202f,
     0.0f,           0.19509032202f,  0.38268343237f,  0.55557023302f,
     0.70710678119f, 0.83146961230f,  0.92387953251f,  0.98078528040f
};

// Shapes (hardcoded, validated against metadata)
#define TT   32      // T
#define DD   128     // d_model
#define EE   9       // experts
#define HWW  256     // H*W
#define NTOK 512     // B*H*W

__global__ __launch_bounds__(256, 4)
void moe_fused_kernel(const float* __restrict__ x,
                      const float* __restrict__ w_fuse,
                      const float* __restrict__ b_fuse,
                      const float* __restrict__ w_gate,
                      const float* __restrict__ We,
                      const float* __restrict__ be,
                      float* __restrict__ out)
{
    // xDup[d][t]: duplicated-pair activations {v,v} as u64, padded pitch 33 to
    // kill STS bank conflicts.  Reused 3x:
    //   phase 1: x tile (input to fuse GEMM)
    //   phase 2: xp tile (input to DFT gating + expert GEMMs)
    //   phase 3: reinterpreted as float ybuf[2][32][128] (expert outputs)
    __shared__ __align__(16) unsigned long long xDup[DD * 33];      // 33792 B
    __shared__ float cosTab[32];
    __shared__ float wgS[16 * EE];       // w_gate [16][9]
    __shared__ float shRed[8 * EE];      // per-warp gating partials
    __shared__ int   shE[2];
    __shared__ float shG[2];

    const int n   = blockIdx.x;
    const int tid = threadIdx.x;

    const int b  = n >> 8;       // n / (H*W)
    const int hw = n & 255;

    // ---- stage 0: small tables + x tile load -------------------------------
    if (tid < 32)                 cosTab[tid]    = g_cos32[tid];
    if (tid >= 32 && tid < 32 + 16 * EE) wgS[tid - 32] = w_gate[tid - 32];

    // x[b, t, 0, h, w, :] -> row base = ((b*T + t)*256 + hw) * 128
    #pragma unroll
    for (int k = 0; k < 16; k++) {
        int idx = k * 256 + tid;
        int t = idx >> 7, d = idx & 127;
        float v = x[((((b * TT + t) << 8) + hw) << 7) + d];
        xDup[d * 33 + t] = dup_f32(v);
    }
    __syncthreads();

    // ---- stage 1: fuse GEMM  xp[t][f] = sum_d x[t][d] * w_fuse[d][f] + b ---
    // thread owns column pair (2c, 2c+1), t-range q*8 .. q*8+7
    const int c = tid & 63;
    const int q = tid >> 6;
    unsigned long long acc[8];
    {
        const unsigned long long* wf2 = (const unsigned long long*)w_fuse;
        unsigned long long binit = ((const unsigned long long*)b_fuse)[c];
        #pragma unroll
        for (int j = 0; j < 8; j++) acc[j] = binit;
        #pragma unroll 4
        for (int d = 0; d < DD; d++) {
            unsigned long long w2 = __ldg(wf2 + d * 64 + c);
            const unsigned long long* xr = &xDup[d * 33 + q * 8];
            #pragma unroll
            for (int j = 0; j < 8; j++) FFMA2(acc[j], xr[j], w2, acc[j]);
        }
    }
    __syncthreads();   // everyone done reading x tile

    // write xp back into xDup as duplicated pairs, indexed [f][t]
    #pragma unroll
    for (int j = 0; j < 8; j++) {
        float lo, hi;
        unpack_f32x2(acc[j], lo, hi);
        int t = q * 8 + j;
        xDup[(2 * c)     * 33 + t] = dup_f32(lo);
        xDup[(2 * c + 1) * 33 + t] = dup_f32(hi);
    }
    __syncthreads();

    // ---- stage 2: rFFT (ortho, drop DC) gating -----------------------------
    // thread handles model-dim d = tid&127, freq half = tid>>7 (bins 1..8 / 9..16)
    {
        const int d    = tid & 127;
        const int half = tid >> 7;
        float xr[TT];
        const float* xpcol = (const float*)&xDup[d * 33];
        #pragma unroll
        for (int t = 0; t < TT; t++) xr[t] = xpcol[2 * t];   // lo lane of pair

        float acc9[EE];
        #pragma unroll
        for (int e = 0; e < EE; e++) acc9[e] = 0.0f;

        #pragma unroll
        for (int jf = 0; jf < 8; jf++) {
            int fb = half * 8 + 1 + jf;           // bin 1..16
            float re = 0.0f, im = 0.0f;
            #pragma unroll
            for (int t = 0; t < TT; t++) {
                int k = (fb * t) & 31;
                re = fmaf(xr[t], cosTab[k], re);
                im = fmaf(xr[t], cosTab[(k + 24) & 31], im);
            }
            // ortho norm: 1/sqrt(32)
            float amp = sqrtf(fmaf(re, re, im * im)) * 0.17677669529663688f;
            const float* wrow = &wgS[(fb - 1) * EE];
            #pragma unroll
            for (int e = 0; e < EE; e++) acc9[e] = fmaf(amp, wrow[e], acc9[e]);
        }

        // deterministic reduction: warp shuffle -> per-warp partials -> thread 0
        #pragma unroll
        for (int e = 0; e < EE; e++) {
            float v = acc9[e];
            v += __shfl_down_sync(0xffffffffu, v, 16);
            v += __shfl_down_sync(0xffffffffu, v, 8);
            v += __shfl_down_sync(0xffffffffu, v, 4);
            v += __shfl_down_sync(0xffffffffu, v, 2);
            v += __shfl_down_sync(0xffffffffu, v, 1);
            if ((tid & 31) == 0) shRed[(tid >> 5) * EE + e] = v;
        }
    }
    __syncthreads();

    if (tid == 0) {
        // weights[e] = mean over d  (sum / 128); top-2 (ties -> lower index,
        // matching jax.lax.top_k), softmax over the two.
        float w0 = -1e30f, w1 = -1e30f;
        int e0 = 0, e1 = 0;
        #pragma unroll
        for (int e = 0; e < EE; e++) {
            float s = 0.0f;
            #pragma unroll
            for (int w = 0; w < 8; w++) s += shRed[w * EE + e];
            float v = s * (1.0f / 128.0f);
            if (v > w0)      { w1 = w0; e1 = e0; w0 = v; e0 = e; }
            else if (v > w1) { w1 = v; e1 = e; }
        }
        float qv  = __expf(w1 - w0);      // <= 1
        float inv = 1.0f / (1.0f + qv);
        shE[0] = e0; shE[1] = e1;
        shG[0] = inv; shG[1] = qv * inv;
    }
    __syncthreads();

    // ---- stage 3: two routed expert GEMMs ----------------------------------
    // group gid = tid>>7 handles expert shE[gid]; within group: col pair cc,
    // t-half hh (16 rows), acc2[16].
    const int gid = tid >> 7;
    const int idx = tid & 127;
    const int cc  = idx & 63;
    const int hh  = idx >> 6;
    const int e   = shE[gid];
    const float gA = shG[0], gB = shG[1];

    unsigned long long yacc[16];
    {
        const unsigned long long* We2 = (const unsigned long long*)We + (size_t)e * (DD * 64);
        unsigned long long binit = ((const unsigned long long*)be)[e * 64 + cc];
        #pragma unroll
        for (int j = 0; j < 16; j++) yacc[j] = binit;
        #pragma unroll 2
        for (int d = 0; d < DD; d++) {
            unsigned long long w2 = __ldg(We2 + d * 64 + cc);
            const unsigned long long* xr = &xDup[d * 33 + hh * 16];
            #pragma unroll
            for (int j = 0; j < 16; j++) FFMA2(yacc[j], xr[j], w2, yacc[j]);
        }
    }
    __syncthreads();   // both groups done reading xp

    // reuse xDup storage as ybuf[2][32][128] (float)
    float* ybuf = (float*)xDup;
    #pragma unroll
    for (int j = 0; j < 16; j++) {
        int t = hh * 16 + j;
        *(unsigned long long*)&ybuf[gid * 4096 + t * 128 + 2 * cc] = yacc[j];
    }
    __syncthreads();

    // ---- stage 4: log-sum-exp combine + store ------------------------------
    // out[n,t,f] = log(gA*exp(y0) + gB*exp(y1))
    //           = m + log(g_max + g_min * exp(y_min - m)),  m = max(y0,y1)
    const float* y0p = ybuf;
    const float* y1p = ybuf + 4096;
    float* outp = out + (size_t)n * 4096;
    #pragma unroll
    for (int k = 0; k < 16; k++) {
        int i = k * 256 + tid;
        float ya = y0p[i], yb = y1p[i];
        bool  sel = (ya >= yb);
        float m   = sel ? ya : yb;
        float gm  = sel ? gA : gB;
        float go  = sel ? gB : gA;
        float dlt = (sel ? yb : ya) - m;
        float ex  = exp_neg_fast(dlt);
        outp[i] = m + __logf(fmaf(go, ex, gm));
    }
}

extern "C" void kernel_launch(void* const* d_in, const int* in_sizes, int n_in,
                              void* d_out, int out_size)
{
    const float* x      = (const float*)d_in[0];
    const float* w_fuse = (const float*)d_in[1];
    const float* b_fuse = (const float*)d_in[2];
    const float* w_gate = (const float*)d_in[3];
    const float* We     = (const float*)d_in[4];
    const float* be     = (const float*)d_in[5];
    float* out = (float*)d_out;

    moe_fused_kernel<<<NTOK, 256>>>(x, w_fuse, b_fuse, w_gate, We, be, out);
}